// round 16
// baseline (speedup 1.0000x reference)
#include <cuda_runtime.h>
#include <cuda_bf16.h>
#include <cstdint>
#include <math.h>

#define BB 4
#define CC 512
#define SS 2048
#define HH 8
#define DD 64
#define NPB (CC*SS)

typedef __nv_bfloat16 bf16;

// softmax: Q pre-scaled by 0.125*log2(e) at e4m3 quantization -> p = ex2(score)
#define QPRESCALE 0.18033688011112042f
#define ONES_BF16X2 0x3F803F80u

// ---------------- static device scratch ----------------
__device__ float g_part[128 * 2];
__device__ bf16 g_h[BB * SS * CC];          // normalized, [B,S,C]
__device__ bf16 g_w[4 * CC * CC];           // wq,wk,wv,wo bf16
__device__ uint8_t g_q8[BB * HH * SS * DD]; // e4m3 [B,H,S,D] (pre-scaled)
__device__ uint8_t g_k8[BB * HH * SS * DD]; // e4m3 [B,H,S,D]
__device__ bf16 g_v[BB * HH * SS * DD];     // bf16 [B,H,S,D]
__device__ bf16 g_o[BB * SS * CC];          // attention out, [B,S,C]

// ---------------- low-level helpers ----------------
__device__ __forceinline__ uint32_t smem_u32(const void* p) {
    uint32_t a;
    asm("{ .reg .u64 t; cvta.to.shared.u64 t, %1; cvt.u32.u64 %0, t; }" : "=r"(a) : "l"(p));
    return a;
}
__device__ __forceinline__ void ldsm4(uint32_t* r, uint32_t addr) {
    asm volatile("ldmatrix.sync.aligned.m8n8.x4.shared.b16 {%0,%1,%2,%3}, [%4];"
                 : "=r"(r[0]), "=r"(r[1]), "=r"(r[2]), "=r"(r[3]) : "r"(addr));
}
__device__ __forceinline__ void ldsm4t(uint32_t* r, uint32_t addr) {
    asm volatile("ldmatrix.sync.aligned.m8n8.x4.trans.shared.b16 {%0,%1,%2,%3}, [%4];"
                 : "=r"(r[0]), "=r"(r[1]), "=r"(r[2]), "=r"(r[3]) : "r"(addr));
}
__device__ __forceinline__ void mma16816(float* c, const uint32_t* a, uint32_t b0, uint32_t b1) {
    asm volatile("mma.sync.aligned.m16n8k16.row.col.f32.bf16.bf16.f32 "
                 "{%0,%1,%2,%3}, {%4,%5,%6,%7}, {%8,%9}, {%0,%1,%2,%3};"
                 : "+f"(c[0]), "+f"(c[1]), "+f"(c[2]), "+f"(c[3])
                 : "r"(a[0]), "r"(a[1]), "r"(a[2]), "r"(a[3]), "r"(b0), "r"(b1));
}
__device__ __forceinline__ void mma_fp8(float* c, const uint32_t* a, uint32_t b0, uint32_t b1) {
    asm volatile("mma.sync.aligned.m16n8k32.row.col.f32.e4m3.e4m3.f32 "
                 "{%0,%1,%2,%3}, {%4,%5,%6,%7}, {%8,%9}, {%0,%1,%2,%3};"
                 : "+f"(c[0]), "+f"(c[1]), "+f"(c[2]), "+f"(c[3])
                 : "r"(a[0]), "r"(a[1]), "r"(a[2]), "r"(a[3]), "r"(b0), "r"(b1));
}
__device__ __forceinline__ uint32_t pack_bf16x2(float lo, float hi) {
    uint32_t r;
    asm("cvt.rn.bf16x2.f32 %0, %1, %2;" : "=r"(r) : "f"(hi), "f"(lo));
    return r;
}
__device__ __forceinline__ uint16_t f2e4m3x2(float lo, float hi) {
    uint16_t r;
    asm("cvt.rn.satfinite.e4m3x2.f32 %0, %1, %2;" : "=h"(r) : "f"(hi), "f"(lo));
    return r;
}
__device__ __forceinline__ float ex2(float x) {
    float r;
    asm("ex2.approx.f32 %0, %1;" : "=f"(r) : "f"(x));
    return r;
}
__device__ __forceinline__ void cp16(uint32_t dst, const void* src) {
    asm volatile("cp.async.cg.shared.global [%0], [%1], 16;" :: "r"(dst), "l"(src));
}
#define CP_COMMIT() asm volatile("cp.async.commit_group;" ::: "memory")
#define CP_WAIT0()  asm volatile("cp.async.wait_group 0;" ::: "memory")
#define CP_WAIT1()  asm volatile("cp.async.wait_group 1;" ::: "memory")

// ---------------- fused: GroupNorm partials + weight bf16 convert ----------------
__global__ void prep(const float* __restrict__ x,
                     const float* __restrict__ wq, const float* __restrict__ wk,
                     const float* __restrict__ wv, const float* __restrict__ wo) {
    if (blockIdx.x >= 128) {
        int i = (blockIdx.x - 128) * 256 + threadIdx.x;
        g_w[0 * CC * CC + i] = __float2bfloat16(wq[i]);
        g_w[1 * CC * CC + i] = __float2bfloat16(wk[i]);
        g_w[2 * CC * CC + i] = __float2bfloat16(wv[i]);
        g_w[3 * CC * CC + i] = __float2bfloat16(wo[i]);
        return;
    }
    int b = blockIdx.x >> 5;
    int chunk = blockIdx.x & 31;
    const float4* p = (const float4*)(x + (size_t)b * NPB + (size_t)chunk * 32768);
    float s = 0.f, s2 = 0.f;
    for (int i = threadIdx.x; i < 8192; i += 256) {
        float4 v = p[i];
        s += v.x + v.y + v.z + v.w;
        s2 += v.x * v.x + v.y * v.y + v.z * v.z + v.w * v.w;
    }
    __shared__ float sh[256], sh2[256];
    sh[threadIdx.x] = s; sh2[threadIdx.x] = s2;
    __syncthreads();
    for (int off = 128; off > 0; off >>= 1) {
        if (threadIdx.x < off) {
            sh[threadIdx.x] += sh[threadIdx.x + off];
            sh2[threadIdx.x] += sh2[threadIdx.x + off];
        }
        __syncthreads();
    }
    if (threadIdx.x == 0) {
        g_part[blockIdx.x * 2 + 0] = sh[0];
        g_part[blockIdx.x * 2 + 1] = sh2[0];
    }
}

// ---------------- normalize + transpose (stats finalized in-block) ----------------
__global__ void norm_convert(const float* __restrict__ x,
                             const float* __restrict__ gw,
                             const float* __restrict__ gb) {
    __shared__ float tile[32][33];
    __shared__ float s_stats[2];
    int b = blockIdx.z;
    int c0 = blockIdx.y * 32;
    int s0 = blockIdx.x * 32;
    tile[threadIdx.y][threadIdx.x] =
        x[((size_t)b * CC + c0 + threadIdx.y) * SS + s0 + threadIdx.x];
    if (threadIdx.y == 0) {
        float s  = g_part[(b * 32 + threadIdx.x) * 2 + 0];
        float s2 = g_part[(b * 32 + threadIdx.x) * 2 + 1];
#pragma unroll
        for (int off = 16; off > 0; off >>= 1) {
            s  += __shfl_xor_sync(0xFFFFFFFF, s, off);
            s2 += __shfl_xor_sync(0xFFFFFFFF, s2, off);
        }
        if (threadIdx.x == 0) {
            float mean = s / (float)NPB;
            float var = s2 / (float)NPB - mean * mean;
            s_stats[0] = mean;
            s_stats[1] = rsqrtf(var + 1e-5f);
        }
    }
    __syncthreads();
    float mean = s_stats[0], inv = s_stats[1];
    int c = c0 + threadIdx.x;
    float scale = gw[c] * inv;
    float shift = gb[c] - mean * scale;
    float t = tile[threadIdx.x][threadIdx.y];
    g_h[((size_t)b * SS + s0 + threadIdx.y) * CC + c] = __float2bfloat16(t * scale + shift);
}

// ---------------- HMMA bf16 NT GEMM, K-tile 64, 3-stage cp.async ----------------
#define GSTR 72
#define GTB (128 * GSTR * 2)      // 18432 bytes per matrix per stage
#define G_SMEM_BYTES (6 * GTB)    // 3 stages x (A+B)

__device__ __forceinline__ void gemm_core(const bf16* __restrict__ A,
                                          const bf16* __restrict__ W,
                                          int m0, int n0, float c[2][8][4],
                                          char* smem) {
    int tid = threadIdx.x;
    int lane = tid & 31;
    int wid = tid >> 5;
    int wm = wid >> 1, wn = wid & 1;
    uint32_t sA = smem_u32(smem);
    uint32_t sB = sA + 3 * GTB;

#pragma unroll
    for (int i = 0; i < 2; i++)
#pragma unroll
        for (int j = 0; j < 8; j++)
#pragma unroll
            for (int k = 0; k < 4; k++) c[i][j][k] = 0.f;

    int r = tid >> 1;
    int half = (tid & 1) * 32;
    const bf16* Ag = A + (size_t)(m0 + r) * 512 + half;
    const bf16* Wg = W + (size_t)(n0 + r) * 512 + half;
    uint32_t dOff = (uint32_t)r * 144 + (uint32_t)half * 2;

#define GPF(kt) do { \
        uint32_t _b = (uint32_t)((kt) % 3) * GTB; \
        const bf16* _An = Ag + (kt) * 64; \
        const bf16* _Wn = Wg + (kt) * 64; \
        cp16(sA + _b + dOff,      _An);      cp16(sA + _b + dOff + 16, _An + 8); \
        cp16(sA + _b + dOff + 32, _An + 16); cp16(sA + _b + dOff + 48, _An + 24); \
        cp16(sB + _b + dOff,      _Wn);      cp16(sB + _b + dOff + 16, _Wn + 8); \
        cp16(sB + _b + dOff + 32, _Wn + 16); cp16(sB + _b + dOff + 48, _Wn + 24); \
        CP_COMMIT(); \
    } while (0)

    GPF(0); GPF(1);

    for (int kt = 0; kt < 8; kt++) {
        CP_WAIT1();
        __syncthreads();
        if (kt < 6) GPF(kt + 2); else CP_COMMIT();
        uint32_t bo = (uint32_t)(kt % 3) * GTB;
#pragma unroll
        for (int ks = 0; ks < 4; ks++) {
            uint32_t a[2][4];
#pragma unroll
            for (int mt = 0; mt < 2; mt++) {
                uint32_t row = wm * 32 + mt * 16 + (lane & 15);
                uint32_t col = ks * 16 + (lane >> 4) * 8;
                ldsm4(a[mt], sA + bo + row * 144 + col * 2);
            }
#pragma unroll
            for (int p = 0; p < 4; p++) {
                uint32_t t4[4];
                uint32_t row = wn * 64 + p * 16 + (lane & 7) + ((lane >> 4) << 3);
                uint32_t col = ks * 16 + (((lane >> 3) & 1) << 3);
                ldsm4(t4, sB + bo + row * 144 + col * 2);
#pragma unroll
                for (int mt = 0; mt < 2; mt++) {
                    mma16816(c[mt][2 * p],     a[mt], t4[0], t4[1]);
                    mma16816(c[mt][2 * p + 1], a[mt], t4[2], t4[3]);
                }
            }
        }
    }
#undef GPF
}

// QKV projection: q (pre-scaled),k -> e4m3 [B,H,S,D]; v -> bf16 [B,H,S,D].
__global__ void __launch_bounds__(256, 2) gemm_qkv(const float* __restrict__ bq,
                                                   const float* __restrict__ bk,
                                                   const float* __restrict__ bv) {
    extern __shared__ char gsm[];
    int z = blockIdx.z;
    int m0 = blockIdx.y * 128, n0 = blockIdx.x * 128;
    const float* bias = (z == 0) ? bq : (z == 1) ? bk : bv;
    float qs = (z == 0) ? QPRESCALE : 1.0f;

    float c[2][8][4];
    gemm_core(g_h, g_w + (size_t)z * CC * CC, m0, n0, c, gsm);

    int lane = threadIdx.x & 31;
    int wid = threadIdx.x >> 5;
    int wm = wid >> 1, wn = wid & 1;
#pragma unroll
    for (int mt = 0; mt < 2; mt++) {
        int r0 = m0 + wm * 32 + mt * 16 + (lane >> 2);
        int b0i = r0 >> 11, s0i = r0 & 2047;
        int r1 = r0 + 8;
        int b1i = r1 >> 11, s1i = r1 & 2047;
#pragma unroll
        for (int nt = 0; nt < 8; nt++) {
            int n = n0 + wn * 64 + nt * 8 + (lane & 3) * 2;
            float bv0 = bias[n], bv1 = bias[n + 1];
            int h = n >> 6, d = n & 63;
            if (z < 2) {
                uint8_t* dst8 = (z == 0) ? g_q8 : g_k8;
                uint16_t v0 = f2e4m3x2((c[mt][nt][0] + bv0) * qs, (c[mt][nt][1] + bv1) * qs);
                uint16_t v1 = f2e4m3x2((c[mt][nt][2] + bv0) * qs, (c[mt][nt][3] + bv1) * qs);
                *(uint16_t*)&dst8[(((size_t)b0i * HH + h) * SS + s0i) * DD + d] = v0;
                *(uint16_t*)&dst8[(((size_t)b1i * HH + h) * SS + s1i) * DD + d] = v1;
            } else {
                uint32_t v0 = pack_bf16x2(c[mt][nt][0] + bv0, c[mt][nt][1] + bv1);
                uint32_t v1 = pack_bf16x2(c[mt][nt][2] + bv0, c[mt][nt][3] + bv1);
                *(uint32_t*)&g_v[(((size_t)b0i * HH + h) * SS + s0i) * DD + d] = v0;
                *(uint32_t*)&g_v[(((size_t)b1i * HH + h) * SS + s1i) * DD + d] = v1;
            }
        }
    }
}

// Output projection: fp32 out [B,C,S] = A@wo^T + bo + residual
__global__ void __launch_bounds__(256, 2) gemm_out(const float* __restrict__ bias,
                                                   const float* __restrict__ resid,
                                                   float* __restrict__ outp) {
    extern __shared__ char gsm[];
    int m0 = blockIdx.y * 128, n0 = blockIdx.x * 128;

    float c[2][8][4];
    gemm_core(g_o, g_w + (size_t)3 * CC * CC, m0, n0, c, gsm);

    int lane = threadIdx.x & 31;
    int wid = threadIdx.x >> 5;
    int wm = wid >> 1, wn = wid & 1;
#pragma unroll
    for (int mt = 0; mt < 2; mt++) {
        int r0 = m0 + wm * 32 + mt * 16 + (lane >> 2);
#pragma unroll
        for (int half = 0; half < 2; half++) {
            int m = r0 + half * 8;
            int b = m >> 11, s = m & 2047;
#pragma unroll
            for (int nt = 0; nt < 8; nt++) {
                int n = n0 + wn * 64 + nt * 8 + (lane & 3) * 2;
                size_t oi0 = ((size_t)b * CC + n) * SS + s;
                size_t oi1 = oi0 + SS;
                outp[oi0] = c[mt][nt][2 * half + 0] + bias[n]     + resid[oi0];
                outp[oi1] = c[mt][nt][2 * half + 1] + bias[n + 1] + resid[oi1];
            }
        }
    }
}

// ---------------- flash attention: fp8 QK + bf16 PV, minimal issue count ---
// 256 thr (8 warps x 16 q). K e4m3 smem (stride 80); V bf16 smem (stride 144);
// Q e4m3 A-frags direct from gmem (pre-scaled: p = ex2(score), no FMUL).
// l via ones-mma on tensor pipe (no FADD chain, no epilogue shuffles).
#define KSTR 80
#define KTB (128 * KSTR)              // 10240 per K buffer
#define VSTR 144
#define VTB (128 * VSTR)              // 18432 per V buffer
#define A_SMEM_BYTES (2 * KTB + 2 * VTB)   // 57344

__global__ void __launch_bounds__(256, 2) attn_mma() {
    extern __shared__ char asmem[];
    uint32_t sK = smem_u32(asmem);           // K0, K1
    uint32_t sV = sK + 2 * KTB;              // V0, V1

    int tid = threadIdx.x;
    int lane = tid & 31;
    int wid = tid >> 5;
    int bh = blockIdx.y;
    int q0 = blockIdx.x * 128;

    const uint8_t* Qg = g_q8 + ((size_t)bh * SS + q0) * DD;
    const uint8_t* Kg = g_k8 + (size_t)bh * SS * DD;
    const bf16*    Vg = g_v  + (size_t)bh * SS * DD;

    int r = tid >> 1;
    int kh = (tid & 1) * 32;                 // K: 32 bytes per thread
    int vh = (tid & 1) * 32;                 // V: 32 elements = 64 bytes
    uint32_t kOff = (uint32_t)(r * KSTR + kh);
    uint32_t vOff = (uint32_t)(r * VSTR + vh * 2);
    const uint8_t* Kt = Kg + (size_t)r * DD + kh;
    const bf16*    Vt = Vg + (size_t)r * DD + vh;

    // prefetch K/V tile 0 into buffer 0
    cp16(sK + kOff, Kt);  cp16(sK + kOff + 16, Kt + 16);
#pragma unroll
    for (int j = 0; j < 4; j++) cp16(sV + vOff + j * 16, Vt + j * 8);
    CP_COMMIT();

    // Q fragments direct from gmem (e4m3 k32 A layout: 4B regs)
    uint32_t aq[2][4];
    {
        int lr = lane >> 2, lc4 = (lane & 3) * 4;
        const uint8_t* q0p = Qg + (size_t)(wid * 16 + lr) * DD + lc4;
        const uint8_t* q8p = q0p + 8 * DD;
#pragma unroll
        for (int ch = 0; ch < 2; ch++) {
            aq[ch][0] = *(const uint32_t*)(q0p + ch * 32);
            aq[ch][1] = *(const uint32_t*)(q8p + ch * 32);
            aq[ch][2] = *(const uint32_t*)(q0p + ch * 32 + 16);
            aq[ch][3] = *(const uint32_t*)(q8p + ch * 32 + 16);
        }
    }

    float o[8][4];
#pragma unroll
    for (int i = 0; i < 8; i++)
#pragma unroll
        for (int j = 0; j < 4; j++) o[i][j] = 0.f;
    float o_l[4] = {0.f, 0.f, 0.f, 0.f};   // rowsums via ones-mma

    uint32_t vrsub = (lane & 15);
    uint32_t vcsub = (lane >> 4) * 8;

    for (int kt = 0; kt < 16; kt++) {
        uint32_t boK = (uint32_t)(kt & 1) * KTB;
        uint32_t boV = (uint32_t)(kt & 1) * VTB;
        CP_WAIT0();
        __syncthreads();
        if (kt < 15) {
            uint32_t bnK = (uint32_t)((kt + 1) & 1) * KTB;
            uint32_t bnV = (uint32_t)((kt + 1) & 1) * VTB;
            const uint8_t* Kn = Kt + (size_t)(kt + 1) * 128 * DD;
            const bf16*    Vn = Vt + (size_t)(kt + 1) * 128 * DD;
            cp16(sK + bnK + kOff, Kn);  cp16(sK + bnK + kOff + 16, Kn + 16);
#pragma unroll
            for (int j = 0; j < 4; j++) cp16(sV + bnV + vOff + j * 16, Vn + j * 8);
            CP_COMMIT();
        }

#pragma unroll
        for (int g = 0; g < 2; g++) {
            uint32_t gbase = (uint32_t)g * 64;
            // ---- QK phase: 64 keys, fp8 k32 (8 ldsm, 16 mma) ----
            float c[8][4];
#pragma unroll
            for (int i = 0; i < 8; i++)
#pragma unroll
                for (int j = 0; j < 4; j++) c[i][j] = 0.f;
#pragma unroll
            for (int ch = 0; ch < 2; ch++) {
#pragma unroll
                for (int s = 0; s < 4; s++) {
                    uint32_t t4[4];
                    uint32_t row = gbase + s * 16 + (lane & 15);
                    ldsm4(t4, sK + boK + row * KSTR + (lane >> 4) * 16 + ch * 32);
                    mma_fp8(c[2 * s],     aq[ch], t4[0], t4[2]);
                    mma_fp8(c[2 * s + 1], aq[ch], t4[1], t4[3]);
                }
            }
            // ---- softmax phase: 32 batched ex2 (no scale FMUL) ----
            uint32_t ap[4][4];
#pragma unroll
            for (int s = 0; s < 4; s++) {
                float p00 = ex2(c[2 * s][0]),     p01 = ex2(c[2 * s][1]);
                float p02 = ex2(c[2 * s][2]),     p03 = ex2(c[2 * s][3]);
                float p10 = ex2(c[2 * s + 1][0]), p11 = ex2(c[2 * s + 1][1]);
                float p12 = ex2(c[2 * s + 1][2]), p13 = ex2(c[2 * s + 1][3]);
                ap[s][0] = pack_bf16x2(p00, p01);
                ap[s][1] = pack_bf16x2(p02, p03);
                ap[s][2] = pack_bf16x2(p10, p11);
                ap[s][3] = pack_bf16x2(p12, p13);
            }
            // ---- PV phase: bf16, 8 o chains + l rowsums via ones-mma ----
#pragma unroll
            for (int s = 0; s < 4; s++) {
                mma16816(o_l, ap[s], ONES_BF16X2, ONES_BF16X2);
#pragma unroll
                for (int dp = 0; dp < 4; dp++) {
                    uint32_t t4[4];
                    uint32_t row = gbase + s * 16 + vrsub;
                    uint32_t col = dp * 16 + vcsub;
                    ldsm4t(t4, sV + boV + row * VSTR + col * 2);
                    mma16816(o[2 * dp],     ap[s], t4[0], t4[1]);
                    mma16816(o[2 * dp + 1], ap[s], t4[2], t4[3]);
                }
            }
        }
    }

    // epilogue: l = rowsums in o_l (ones-B makes quad lanes identical)
    float invl0 = 1.f / o_l[0];
    float invl1 = 1.f / o_l[2];

    int b = bh >> 3, h = bh & 7;
    int row0 = q0 + wid * 16 + (lane >> 2);
    bf16* out0 = g_o + ((size_t)b * SS + row0) * CC + h * DD;
    bf16* out1 = g_o + ((size_t)b * SS + row0 + 8) * CC + h * DD;
#pragma unroll
    for (int nt = 0; nt < 8; nt++) {
        int d = nt * 8 + (lane & 3) * 2;
        *(uint32_t*)&out0[d] = pack_bf16x2(o[nt][0] * invl0, o[nt][1] * invl0);
        *(uint32_t*)&out1[d] = pack_bf16x2(o[nt][2] * invl1, o[nt][3] * invl1);
    }
}

// ---------------- launch ----------------
extern "C" void kernel_launch(void* const* d_in, const int* in_sizes, int n_in,
                              void* d_out, int out_size) {
    const float* x  = (const float*)d_in[0];
    const float* gw = (const float*)d_in[1];
    const float* gb = (const float*)d_in[2];
    const float* wq = (const float*)d_in[3];
    const float* bq = (const float*)d_in[4];
    const float* wk = (const float*)d_in[5];
    const float* bk = (const float*)d_in[6];
    const float* wv = (const float*)d_in[7];
    const float* bv = (const float*)d_in[8];
    const float* wo = (const float*)d_in[9];
    const float* bo = (const float*)d_in[10];
    float* out = (float*)d_out;

    cudaFuncSetAttribute(attn_mma, cudaFuncAttributeMaxDynamicSharedMemorySize, A_SMEM_BYTES);
    cudaFuncSetAttribute(gemm_qkv, cudaFuncAttributeMaxDynamicSharedMemorySize, G_SMEM_BYTES);
    cudaFuncSetAttribute(gemm_out, cudaFuncAttributeMaxDynamicSharedMemorySize, G_SMEM_BYTES);

    prep<<<128 + 1024, 256>>>(x, wq, wk, wv, wo);
    norm_convert<<<dim3(SS / 32, CC / 32, BB), dim3(32, 32)>>>(x, gw, gb);

    gemm_qkv<<<dim3(CC / 128, BB * SS / 128, 3), 256, G_SMEM_BYTES>>>(bq, bk, bv);

    attn_mma<<<dim3(SS / 128, BB * HH), 256, A_SMEM_BYTES>>>();

    gemm_out<<<dim3(CC / 128, BB * SS / 128), 256, G_SMEM_BYTES>>>(bo, x, out);
}

// round 17
// speedup vs baseline: 1.4969x; 1.4969x over previous
#include <cuda_runtime.h>
#include <cuda_bf16.h>
#include <cstdint>
#include <math.h>

#define BB 4
#define CC 512
#define SS 2048
#define HH 8
#define DD 64
#define NPB (CC*SS)

typedef __nv_bfloat16 bf16;

// softmax: Q pre-scaled by 0.125*log2(e) at e4m3 quantization -> p = ex2(score)
#define QPRESCALE 0.18033688011112042f

// ---------------- static device scratch ----------------
__device__ float g_part[128 * 2];
__device__ bf16 g_h[BB * SS * CC];          // normalized, [B,S,C]
__device__ bf16 g_w[4 * CC * CC];           // wq,wk,wv,wo bf16
__device__ uint8_t g_q8[BB * HH * SS * DD]; // e4m3 [B,H,S,D] (pre-scaled)
__device__ uint8_t g_k8[BB * HH * SS * DD]; // e4m3 [B,H,S,D]
__device__ bf16 g_v[BB * HH * SS * DD];     // bf16 [B,H,S,D]
__device__ bf16 g_o[BB * SS * CC];          // attention out, [B,S,C]

// ---------------- low-level helpers ----------------
__device__ __forceinline__ uint32_t smem_u32(const void* p) {
    uint32_t a;
    asm("{ .reg .u64 t; cvta.to.shared.u64 t, %1; cvt.u32.u64 %0, t; }" : "=r"(a) : "l"(p));
    return a;
}
__device__ __forceinline__ void ldsm4(uint32_t* r, uint32_t addr) {
    asm volatile("ldmatrix.sync.aligned.m8n8.x4.shared.b16 {%0,%1,%2,%3}, [%4];"
                 : "=r"(r[0]), "=r"(r[1]), "=r"(r[2]), "=r"(r[3]) : "r"(addr));
}
__device__ __forceinline__ void ldsm4t(uint32_t* r, uint32_t addr) {
    asm volatile("ldmatrix.sync.aligned.m8n8.x4.trans.shared.b16 {%0,%1,%2,%3}, [%4];"
                 : "=r"(r[0]), "=r"(r[1]), "=r"(r[2]), "=r"(r[3]) : "r"(addr));
}
__device__ __forceinline__ void mma16816(float* c, const uint32_t* a, uint32_t b0, uint32_t b1) {
    asm volatile("mma.sync.aligned.m16n8k16.row.col.f32.bf16.bf16.f32 "
                 "{%0,%1,%2,%3}, {%4,%5,%6,%7}, {%8,%9}, {%0,%1,%2,%3};"
                 : "+f"(c[0]), "+f"(c[1]), "+f"(c[2]), "+f"(c[3])
                 : "r"(a[0]), "r"(a[1]), "r"(a[2]), "r"(a[3]), "r"(b0), "r"(b1));
}
__device__ __forceinline__ void mma_fp8(float* c, const uint32_t* a, uint32_t b0, uint32_t b1) {
    asm volatile("mma.sync.aligned.m16n8k32.row.col.f32.e4m3.e4m3.f32 "
                 "{%0,%1,%2,%3}, {%4,%5,%6,%7}, {%8,%9}, {%0,%1,%2,%3};"
                 : "+f"(c[0]), "+f"(c[1]), "+f"(c[2]), "+f"(c[3])
                 : "r"(a[0]), "r"(a[1]), "r"(a[2]), "r"(a[3]), "r"(b0), "r"(b1));
}
__device__ __forceinline__ uint32_t pack_bf16x2(float lo, float hi) {
    uint32_t r;
    asm("cvt.rn.bf16x2.f32 %0, %1, %2;" : "=r"(r) : "f"(hi), "f"(lo));
    return r;
}
__device__ __forceinline__ uint16_t f2e4m3x2(float lo, float hi) {
    uint16_t r;
    asm("cvt.rn.satfinite.e4m3x2.f32 %0, %1, %2;" : "=h"(r) : "f"(hi), "f"(lo));
    return r;
}
__device__ __forceinline__ float ex2(float x) {
    float r;
    asm("ex2.approx.f32 %0, %1;" : "=f"(r) : "f"(x));
    return r;
}
__device__ __forceinline__ void cp16(uint32_t dst, const void* src) {
    asm volatile("cp.async.cg.shared.global [%0], [%1], 16;" :: "r"(dst), "l"(src));
}
#define CP_COMMIT() asm volatile("cp.async.commit_group;" ::: "memory")
#define CP_WAIT0()  asm volatile("cp.async.wait_group 0;" ::: "memory")
#define CP_WAIT1()  asm volatile("cp.async.wait_group 1;" ::: "memory")

// ---------------- fused: GroupNorm partials + weight bf16 convert ----------------
__global__ void prep(const float* __restrict__ x,
                     const float* __restrict__ wq, const float* __restrict__ wk,
                     const float* __restrict__ wv, const float* __restrict__ wo) {
    if (blockIdx.x >= 128) {
        int i = (blockIdx.x - 128) * 256 + threadIdx.x;
        g_w[0 * CC * CC + i] = __float2bfloat16(wq[i]);
        g_w[1 * CC * CC + i] = __float2bfloat16(wk[i]);
        g_w[2 * CC * CC + i] = __float2bfloat16(wv[i]);
        g_w[3 * CC * CC + i] = __float2bfloat16(wo[i]);
        return;
    }
    int b = blockIdx.x >> 5;
    int chunk = blockIdx.x & 31;
    const float4* p = (const float4*)(x + (size_t)b * NPB + (size_t)chunk * 32768);
    float s = 0.f, s2 = 0.f;
    for (int i = threadIdx.x; i < 8192; i += 256) {
        float4 v = p[i];
        s += v.x + v.y + v.z + v.w;
        s2 += v.x * v.x + v.y * v.y + v.z * v.z + v.w * v.w;
    }
    __shared__ float sh[256], sh2[256];
    sh[threadIdx.x] = s; sh2[threadIdx.x] = s2;
    __syncthreads();
    for (int off = 128; off > 0; off >>= 1) {
        if (threadIdx.x < off) {
            sh[threadIdx.x] += sh[threadIdx.x + off];
            sh2[threadIdx.x] += sh2[threadIdx.x + off];
        }
        __syncthreads();
    }
    if (threadIdx.x == 0) {
        g_part[blockIdx.x * 2 + 0] = sh[0];
        g_part[blockIdx.x * 2 + 1] = sh2[0];
    }
}

// ---------------- normalize + transpose (stats finalized in-block) ----------------
__global__ void norm_convert(const float* __restrict__ x,
                             const float* __restrict__ gw,
                             const float* __restrict__ gb) {
    __shared__ float tile[32][33];
    __shared__ float s_stats[2];
    int b = blockIdx.z;
    int c0 = blockIdx.y * 32;
    int s0 = blockIdx.x * 32;
    tile[threadIdx.y][threadIdx.x] =
        x[((size_t)b * CC + c0 + threadIdx.y) * SS + s0 + threadIdx.x];
    if (threadIdx.y == 0) {
        float s  = g_part[(b * 32 + threadIdx.x) * 2 + 0];
        float s2 = g_part[(b * 32 + threadIdx.x) * 2 + 1];
#pragma unroll
        for (int off = 16; off > 0; off >>= 1) {
            s  += __shfl_xor_sync(0xFFFFFFFF, s, off);
            s2 += __shfl_xor_sync(0xFFFFFFFF, s2, off);
        }
        if (threadIdx.x == 0) {
            float mean = s / (float)NPB;
            float var = s2 / (float)NPB - mean * mean;
            s_stats[0] = mean;
            s_stats[1] = rsqrtf(var + 1e-5f);
        }
    }
    __syncthreads();
    float mean = s_stats[0], inv = s_stats[1];
    int c = c0 + threadIdx.x;
    float scale = gw[c] * inv;
    float shift = gb[c] - mean * scale;
    float t = tile[threadIdx.x][threadIdx.y];
    g_h[((size_t)b * SS + s0 + threadIdx.y) * CC + c] = __float2bfloat16(t * scale + shift);
}

// ---------------- HMMA bf16 NT GEMM, K-tile 64, 3-stage cp.async ----------------
#define GSTR 72
#define GTB (128 * GSTR * 2)      // 18432 bytes per matrix per stage
#define G_SMEM_BYTES (6 * GTB)    // 3 stages x (A+B)

__device__ __forceinline__ void gemm_core(const bf16* __restrict__ A,
                                          const bf16* __restrict__ W,
                                          int m0, int n0, float c[2][8][4],
                                          char* smem) {
    int tid = threadIdx.x;
    int lane = tid & 31;
    int wid = tid >> 5;
    int wm = wid >> 1, wn = wid & 1;
    uint32_t sA = smem_u32(smem);
    uint32_t sB = sA + 3 * GTB;

#pragma unroll
    for (int i = 0; i < 2; i++)
#pragma unroll
        for (int j = 0; j < 8; j++)
#pragma unroll
            for (int k = 0; k < 4; k++) c[i][j][k] = 0.f;

    int r = tid >> 1;
    int half = (tid & 1) * 32;
    const bf16* Ag = A + (size_t)(m0 + r) * 512 + half;
    const bf16* Wg = W + (size_t)(n0 + r) * 512 + half;
    uint32_t dOff = (uint32_t)r * 144 + (uint32_t)half * 2;

#define GPF(kt) do { \
        uint32_t _b = (uint32_t)((kt) % 3) * GTB; \
        const bf16* _An = Ag + (kt) * 64; \
        const bf16* _Wn = Wg + (kt) * 64; \
        cp16(sA + _b + dOff,      _An);      cp16(sA + _b + dOff + 16, _An + 8); \
        cp16(sA + _b + dOff + 32, _An + 16); cp16(sA + _b + dOff + 48, _An + 24); \
        cp16(sB + _b + dOff,      _Wn);      cp16(sB + _b + dOff + 16, _Wn + 8); \
        cp16(sB + _b + dOff + 32, _Wn + 16); cp16(sB + _b + dOff + 48, _Wn + 24); \
        CP_COMMIT(); \
    } while (0)

    GPF(0); GPF(1);

    for (int kt = 0; kt < 8; kt++) {
        CP_WAIT1();
        __syncthreads();
        if (kt < 6) GPF(kt + 2); else CP_COMMIT();
        uint32_t bo = (uint32_t)(kt % 3) * GTB;
#pragma unroll
        for (int ks = 0; ks < 4; ks++) {
            uint32_t a[2][4];
#pragma unroll
            for (int mt = 0; mt < 2; mt++) {
                uint32_t row = wm * 32 + mt * 16 + (lane & 15);
                uint32_t col = ks * 16 + (lane >> 4) * 8;
                ldsm4(a[mt], sA + bo + row * 144 + col * 2);
            }
#pragma unroll
            for (int p = 0; p < 4; p++) {
                uint32_t t4[4];
                uint32_t row = wn * 64 + p * 16 + (lane & 7) + ((lane >> 4) << 3);
                uint32_t col = ks * 16 + (((lane >> 3) & 1) << 3);
                ldsm4(t4, sB + bo + row * 144 + col * 2);
#pragma unroll
                for (int mt = 0; mt < 2; mt++) {
                    mma16816(c[mt][2 * p],     a[mt], t4[0], t4[1]);
                    mma16816(c[mt][2 * p + 1], a[mt], t4[2], t4[3]);
                }
            }
        }
    }
#undef GPF
}

// QKV projection: q (pre-scaled),k -> e4m3 [B,H,S,D]; v -> bf16 [B,H,S,D].
__global__ void __launch_bounds__(256, 2) gemm_qkv(const float* __restrict__ bq,
                                                   const float* __restrict__ bk,
                                                   const float* __restrict__ bv) {
    extern __shared__ char gsm[];
    int z = blockIdx.z;
    int m0 = blockIdx.y * 128, n0 = blockIdx.x * 128;
    const float* bias = (z == 0) ? bq : (z == 1) ? bk : bv;
    float qs = (z == 0) ? QPRESCALE : 1.0f;

    float c[2][8][4];
    gemm_core(g_h, g_w + (size_t)z * CC * CC, m0, n0, c, gsm);

    int lane = threadIdx.x & 31;
    int wid = threadIdx.x >> 5;
    int wm = wid >> 1, wn = wid & 1;
#pragma unroll
    for (int mt = 0; mt < 2; mt++) {
        int r0 = m0 + wm * 32 + mt * 16 + (lane >> 2);
        int b0i = r0 >> 11, s0i = r0 & 2047;
        int r1 = r0 + 8;
        int b1i = r1 >> 11, s1i = r1 & 2047;
#pragma unroll
        for (int nt = 0; nt < 8; nt++) {
            int n = n0 + wn * 64 + nt * 8 + (lane & 3) * 2;
            float bv0 = bias[n], bv1 = bias[n + 1];
            int h = n >> 6, d = n & 63;
            if (z < 2) {
                uint8_t* dst8 = (z == 0) ? g_q8 : g_k8;
                uint16_t v0 = f2e4m3x2((c[mt][nt][0] + bv0) * qs, (c[mt][nt][1] + bv1) * qs);
                uint16_t v1 = f2e4m3x2((c[mt][nt][2] + bv0) * qs, (c[mt][nt][3] + bv1) * qs);
                *(uint16_t*)&dst8[(((size_t)b0i * HH + h) * SS + s0i) * DD + d] = v0;
                *(uint16_t*)&dst8[(((size_t)b1i * HH + h) * SS + s1i) * DD + d] = v1;
            } else {
                uint32_t v0 = pack_bf16x2(c[mt][nt][0] + bv0, c[mt][nt][1] + bv1);
                uint32_t v1 = pack_bf16x2(c[mt][nt][2] + bv0, c[mt][nt][3] + bv1);
                *(uint32_t*)&g_v[(((size_t)b0i * HH + h) * SS + s0i) * DD + d] = v0;
                *(uint32_t*)&g_v[(((size_t)b1i * HH + h) * SS + s1i) * DD + d] = v1;
            }
        }
    }
}

// Output projection: fp32 out [B,C,S] = A@wo^T + bo + residual
__global__ void __launch_bounds__(256, 2) gemm_out(const float* __restrict__ bias,
                                                   const float* __restrict__ resid,
                                                   float* __restrict__ outp) {
    extern __shared__ char gsm[];
    int m0 = blockIdx.y * 128, n0 = blockIdx.x * 128;

    float c[2][8][4];
    gemm_core(g_o, g_w + (size_t)3 * CC * CC, m0, n0, c, gsm);

    int lane = threadIdx.x & 31;
    int wid = threadIdx.x >> 5;
    int wm = wid >> 1, wn = wid & 1;
#pragma unroll
    for (int mt = 0; mt < 2; mt++) {
        int r0 = m0 + wm * 32 + mt * 16 + (lane >> 2);
#pragma unroll
        for (int half = 0; half < 2; half++) {
            int m = r0 + half * 8;
            int b = m >> 11, s = m & 2047;
#pragma unroll
            for (int nt = 0; nt < 8; nt++) {
                int n = n0 + wn * 64 + nt * 8 + (lane & 3) * 2;
                size_t oi0 = ((size_t)b * CC + n) * SS + s;
                size_t oi1 = oi0 + SS;
                outp[oi0] = c[mt][nt][2 * half + 0] + bias[n]     + resid[oi0];
                outp[oi1] = c[mt][nt][2 * half + 1] + bias[n + 1] + resid[oi1];
            }
        }
    }
}

// ---------------- flash attention: fp8 QK + bf16 PV (R15 structure) -------
// 256 thr (8 warps x 16 q). K e4m3 smem (stride 80, 2 buffers); V bf16 smem
// (stride 144, 2 buffers); Q e4m3 A-frags direct from gmem (pre-scaled ->
// p = ex2(score), zero scale FMULs). l via FADD partials (proven R15 form).
#define KSTR 80
#define KTB (128 * KSTR)              // 10240 per K buffer
#define VSTR 144
#define VTB (128 * VSTR)              // 18432 per V buffer
#define A_SMEM_BYTES (2 * KTB + 2 * VTB)   // 57344

__global__ void __launch_bounds__(256, 2) attn_mma() {
    extern __shared__ char asmem[];
    uint32_t sK = smem_u32(asmem);           // K0, K1
    uint32_t sV = sK + 2 * KTB;              // V0, V1

    int tid = threadIdx.x;
    int lane = tid & 31;
    int wid = tid >> 5;
    int bh = blockIdx.y;
    int q0 = blockIdx.x * 128;

    const uint8_t* Qg = g_q8 + ((size_t)bh * SS + q0) * DD;
    const uint8_t* Kg = g_k8 + (size_t)bh * SS * DD;
    const bf16*    Vg = g_v  + (size_t)bh * SS * DD;

    int r = tid >> 1;
    int kh = (tid & 1) * 32;                 // K: 32 bytes per thread
    int vh = (tid & 1) * 32;                 // V: 32 elements = 64 bytes
    uint32_t kOff = (uint32_t)(r * KSTR + kh);
    uint32_t vOff = (uint32_t)(r * VSTR + vh * 2);
    const uint8_t* Kt = Kg + (size_t)r * DD + kh;
    const bf16*    Vt = Vg + (size_t)r * DD + vh;

    // prefetch K/V tile 0 into buffer 0
    cp16(sK + kOff, Kt);  cp16(sK + kOff + 16, Kt + 16);
#pragma unroll
    for (int j = 0; j < 4; j++) cp16(sV + vOff + j * 16, Vt + j * 8);
    CP_COMMIT();

    // Q fragments direct from gmem (e4m3 k32 A layout: 4B regs)
    uint32_t aq[2][4];
    {
        int lr = lane >> 2, lc4 = (lane & 3) * 4;
        const uint8_t* q0p = Qg + (size_t)(wid * 16 + lr) * DD + lc4;
        const uint8_t* q8p = q0p + 8 * DD;
#pragma unroll
        for (int ch = 0; ch < 2; ch++) {
            aq[ch][0] = *(const uint32_t*)(q0p + ch * 32);
            aq[ch][1] = *(const uint32_t*)(q8p + ch * 32);
            aq[ch][2] = *(const uint32_t*)(q0p + ch * 32 + 16);
            aq[ch][3] = *(const uint32_t*)(q8p + ch * 32 + 16);
        }
    }

    float o[8][4];
#pragma unroll
    for (int i = 0; i < 8; i++)
#pragma unroll
        for (int j = 0; j < 4; j++) o[i][j] = 0.f;
    float la0 = 0.f, la1 = 0.f, lb0 = 0.f, lb1 = 0.f;

    uint32_t vrsub = (lane & 15);
    uint32_t vcsub = (lane >> 4) * 8;

    for (int kt = 0; kt < 16; kt++) {
        uint32_t boK = (uint32_t)(kt & 1) * KTB;
        uint32_t boV = (uint32_t)(kt & 1) * VTB;
        CP_WAIT0();
        __syncthreads();
        if (kt < 15) {
            uint32_t bnK = (uint32_t)((kt + 1) & 1) * KTB;
            uint32_t bnV = (uint32_t)((kt + 1) & 1) * VTB;
            const uint8_t* Kn = Kt + (size_t)(kt + 1) * 128 * DD;
            const bf16*    Vn = Vt + (size_t)(kt + 1) * 128 * DD;
            cp16(sK + bnK + kOff, Kn);  cp16(sK + bnK + kOff + 16, Kn + 16);
#pragma unroll
            for (int j = 0; j < 4; j++) cp16(sV + bnV + vOff + j * 16, Vn + j * 8);
            CP_COMMIT();
        }

#pragma unroll
        for (int g = 0; g < 2; g++) {
            uint32_t gbase = (uint32_t)g * 64;
            // ---- QK phase: 64 keys, fp8 k32 (8 ldsm, 16 mma) ----
            float c[8][4];
#pragma unroll
            for (int i = 0; i < 8; i++)
#pragma unroll
                for (int j = 0; j < 4; j++) c[i][j] = 0.f;
#pragma unroll
            for (int ch = 0; ch < 2; ch++) {
#pragma unroll
                for (int s = 0; s < 4; s++) {
                    uint32_t t4[4];
                    uint32_t row = gbase + s * 16 + (lane & 15);
                    ldsm4(t4, sK + boK + row * KSTR + (lane >> 4) * 16 + ch * 32);
                    mma_fp8(c[2 * s],     aq[ch], t4[0], t4[2]);
                    mma_fp8(c[2 * s + 1], aq[ch], t4[1], t4[3]);
                }
            }
            // ---- softmax phase: 32 batched ex2 (no scale FMUL), 4-way l ----
            uint32_t ap[4][4];
#pragma unroll
            for (int s = 0; s < 4; s++) {
                float p00 = ex2(c[2 * s][0]),     p01 = ex2(c[2 * s][1]);
                float p02 = ex2(c[2 * s][2]),     p03 = ex2(c[2 * s][3]);
                float p10 = ex2(c[2 * s + 1][0]), p11 = ex2(c[2 * s + 1][1]);
                float p12 = ex2(c[2 * s + 1][2]), p13 = ex2(c[2 * s + 1][3]);
                if (s & 1) { lb0 += p00 + p01 + p10 + p11; lb1 += p02 + p03 + p12 + p13; }
                else       { la0 += p00 + p01 + p10 + p11; la1 += p02 + p03 + p12 + p13; }
                ap[s][0] = pack_bf16x2(p00, p01);
                ap[s][1] = pack_bf16x2(p02, p03);
                ap[s][2] = pack_bf16x2(p10, p11);
                ap[s][3] = pack_bf16x2(p12, p13);
            }
            // ---- PV phase: bf16, 8 o chains ----
#pragma unroll
            for (int s = 0; s < 4; s++) {
#pragma unroll
                for (int dp = 0; dp < 4; dp++) {
                    uint32_t t4[4];
                    uint32_t row = gbase + s * 16 + vrsub;
                    uint32_t col = dp * 16 + vcsub;
                    ldsm4t(t4, sV + boV + row * VSTR + col * 2);
                    mma16816(o[2 * dp],     ap[s], t4[0], t4[1]);
                    mma16816(o[2 * dp + 1], ap[s], t4[2], t4[3]);
                }
            }
        }
    }

    // reduce l over the 4-lane quad (lanes sharing a row)
    float l0 = la0 + lb0, l1 = la1 + lb1;
    l0 += __shfl_xor_sync(0xFFFFFFFF, l0, 1);
    l0 += __shfl_xor_sync(0xFFFFFFFF, l0, 2);
    l1 += __shfl_xor_sync(0xFFFFFFFF, l1, 1);
    l1 += __shfl_xor_sync(0xFFFFFFFF, l1, 2);
    float invl0 = 1.f / l0, invl1 = 1.f / l1;

    // write O as bf16 to g_o [B,S,C]
    int b = bh >> 3, h = bh & 7;
    int row0 = q0 + wid * 16 + (lane >> 2);
    bf16* out0 = g_o + ((size_t)b * SS + row0) * CC + h * DD;
    bf16* out1 = g_o + ((size_t)b * SS + row0 + 8) * CC + h * DD;
#pragma unroll
    for (int nt = 0; nt < 8; nt++) {
        int d = nt * 8 + (lane & 3) * 2;
        *(uint32_t*)&out0[d] = pack_bf16x2(o[nt][0] * invl0, o[nt][1] * invl0);
        *(uint32_t*)&out1[d] = pack_bf16x2(o[nt][2] * invl1, o[nt][3] * invl1);
    }
}

// ---------------- launch ----------------
extern "C" void kernel_launch(void* const* d_in, const int* in_sizes, int n_in,
                              void* d_out, int out_size) {
    const float* x  = (const float*)d_in[0];
    const float* gw = (const float*)d_in[1];
    const float* gb = (const float*)d_in[2];
    const float* wq = (const float*)d_in[3];
    const float* bq = (const float*)d_in[4];
    const float* wk = (const float*)d_in[5];
    const float* bk = (const float*)d_in[6];
    const float* wv = (const float*)d_in[7];
    const float* bv = (const float*)d_in[8];
    const float* wo = (const float*)d_in[9];
    const float* bo = (const float*)d_in[10];
    float* out = (float*)d_out;

    cudaFuncSetAttribute(attn_mma, cudaFuncAttributeMaxDynamicSharedMemorySize, A_SMEM_BYTES);
    cudaFuncSetAttribute(gemm_qkv, cudaFuncAttributeMaxDynamicSharedMemorySize, G_SMEM_BYTES);
    cudaFuncSetAttribute(gemm_out, cudaFuncAttributeMaxDynamicSharedMemorySize, G_SMEM_BYTES);

    prep<<<128 + 1024, 256>>>(x, wq, wk, wv, wo);
    norm_convert<<<dim3(SS / 32, CC / 32, BB), dim3(32, 32)>>>(x, gw, gb);

    gemm_qkv<<<dim3(CC / 128, BB * SS / 128, 3), 256, G_SMEM_BYTES>>>(bq, bk, bv);

    attn_mma<<<dim3(SS / 128, BB * HH), 256, A_SMEM_BYTES>>>();

    gemm_out<<<dim3(CC / 128, BB * SS / 128), 256, G_SMEM_BYTES>>>(bo, x, out);
}